// round 16
// baseline (speedup 1.0000x reference)
#include <cuda_runtime.h>
#include <math.h>

#define B_  64
#define C_  512
#define HW_ 4096      // 64*64
#define E_  16
#define K_  4

#define ROWS_PER_BLK 2
#define BLKS_PER_B   (C_ / ROWS_PER_BLK)    // 256 pool blocks per batch

__device__ float g_pooled[B_ * C_];
__device__ int   g_count[B_];               // zero-init; gate resets per replay

// ---------------------------------------------------------------------------
// Pool kernel (champion form + per-block completion signal).
// Row split across 4 warps; block = 2 rows; __ldcs streaming loads.
// ---------------------------------------------------------------------------
__global__ __launch_bounds__(256) void pool_kernel(const float* __restrict__ x) {
    const int tid  = threadIdx.x;
    const int w    = tid >> 5;          // warp 0..7
    const int lane = tid & 31;
    const int rloc = w >> 2;            // row within block (0..1)
    const int q    = w & 3;             // quarter of the row (0..3)
    const int row  = blockIdx.x * 2 + rloc;
    const int b    = blockIdx.x / BLKS_PER_B;

    __shared__ float2 sh[8];            // per-warp (max, sum) partials

    const float4* __restrict__ p =
        reinterpret_cast<const float4*>(x + (size_t)row * HW_) + q * 256 + lane;

    float mx0 = -INFINITY, mx1 = -INFINITY;
    float sm0 = 0.0f, sm1 = 0.0f;
#pragma unroll
    for (int i = 0; i < 8; i += 2) {
        float4 a = __ldcs(p + i * 32);          // streaming: evict-first
        float4 c = __ldcs(p + (i + 1) * 32);
        mx0 = fmaxf(mx0, fmaxf(fmaxf(a.x, a.y), fmaxf(a.z, a.w)));
        sm0 += (a.x + a.y) + (a.z + a.w);
        mx1 = fmaxf(mx1, fmaxf(fmaxf(c.x, c.y), fmaxf(c.z, c.w)));
        sm1 += (c.x + c.y) + (c.z + c.w);
    }
    float mx = fmaxf(mx0, mx1);
    float sm = sm0 + sm1;
#pragma unroll
    for (int o = 16; o; o >>= 1) {
        mx = fmaxf(mx, __shfl_xor_sync(0xffffffffu, mx, o));
        sm += __shfl_xor_sync(0xffffffffu, sm, o);
    }
    if (lane == 0) sh[w] = make_float2(mx, sm);
    __syncthreads();

    if (tid < 2) {                      // thread r combines row r's 4 quarters
        float2 a = sh[tid * 4 + 0], c = sh[tid * 4 + 1];
        float2 d = sh[tid * 4 + 2], e = sh[tid * 4 + 3];
        float m = fmaxf(fmaxf(a.x, c.x), fmaxf(d.x, e.x));
        float s = (a.y + c.y) + (d.y + e.y);
        g_pooled[blockIdx.x * 2 + tid] = m + s * (1.0f / HW_);
    }
    __syncthreads();
    if (tid == 0) {
        __threadfence();                // release g_pooled writes
        atomicAdd(&g_count[b], 1);
    }
}

// ---------------------------------------------------------------------------
// Gate kernel — runs CONCURRENTLY with pool on a parallel graph branch.
// Preloads weights into registers, then spins on its batch's counter.
// 64 blocks x 512 threads; warp e = expert e; warp-parallel epilogue.
// ---------------------------------------------------------------------------
__global__ __launch_bounds__(512) void gate_kernel(const float* __restrict__ W0,
                                                   const float* __restrict__ b0,
                                                   const float* __restrict__ W1,
                                                   const float* __restrict__ b1,
                                                   float* __restrict__ out) {
    const int b    = blockIdx.x;
    const int tid  = threadIdx.x;
    const int e    = tid >> 5;     // expert = warp id (0..15)
    const int lane = tid & 31;

    __shared__ float sh_h[E_];
    __shared__ float sh_n[E_];

    // -------- prologue: overlapped with pooling -----------------------------
    const float4* __restrict__ w0p =
        reinterpret_cast<const float4*>(W0 + e * C_) + lane;
    const float4* __restrict__ w1p =
        reinterpret_cast<const float4*>(W1 + e * C_) + lane;
    float4 w0r[4], w1r[4];
#pragma unroll
    for (int i = 0; i < 4; i++) w0r[i] = w0p[i * 32];
#pragma unroll
    for (int i = 0; i < 4; i++) w1r[i] = w1p[i * 32];
    const float bias0 = b0[e];
    const float bias1 = b1[e];

    // -------- wait for THIS batch's pool blocks -----------------------------
    if (tid == 0) {
        volatile int* cnt = g_count + b;
        while (*cnt < BLKS_PER_B) __nanosleep(128);
        __threadfence();                // acquire batch-b g_pooled writes
    }
    __syncthreads();

    const float4* __restrict__ prow =
        reinterpret_cast<const float4*>(g_pooled + b * C_) + lane;
    float d0 = 0.0f, d1 = 0.0f;
#pragma unroll
    for (int i = 0; i < 4; i++) {
        float4 pv = prow[i * 32];
        d0 = fmaf(pv.x, w0r[i].x, d0); d0 = fmaf(pv.y, w0r[i].y, d0);
        d0 = fmaf(pv.z, w0r[i].z, d0); d0 = fmaf(pv.w, w0r[i].w, d0);
        d1 = fmaf(pv.x, w1r[i].x, d1); d1 = fmaf(pv.y, w1r[i].y, d1);
        d1 = fmaf(pv.z, w1r[i].z, d1); d1 = fmaf(pv.w, w1r[i].w, d1);
    }
#pragma unroll
    for (int o = 16; o; o >>= 1) {
        d0 += __shfl_xor_sync(0xffffffffu, d0, o);
        d1 += __shfl_xor_sync(0xffffffffu, d1, o);
    }
    if (lane == 0) {
        float hv = d0 + bias0;
        sh_h[e] = (hv >= 0.0f) ? hv : 0.2f * hv;                 // LeakyReLU(0.2)
        float z = d1 + bias1;
        sh_n[e] = fmaxf(z, 0.0f) + log1pf(expf(-fabsf(z)));      // softplus
    }
    __syncthreads();

    // ------------- warp-parallel epilogue (warp 0; lane i = expert i) -------
    if (tid < 32) {
        const bool act = lane < E_;
        float h  = act ? sh_h[lane] : 0.0f;
        float nz = act ? sh_n[lane] : 0.0f;

        float s = nz;
#pragma unroll
        for (int o = 8; o; o >>= 1) s += __shfl_xor_sync(0xffffffffu, s, o, 16);
        const float mu = s * (1.0f / E_);

        float d = nz - mu;
        float v = d * d;
#pragma unroll
        for (int o = 8; o; o >>= 1) v += __shfl_xor_sync(0xffffffffu, v, o, 16);
        const float sd = sqrtf(v * (1.0f / (E_ - 1)));   // ddof=1

        float score = act ? (h + d / sd) : -INFINITY;

        // top-K via max + ballot; lowest lane wins ties (= first occurrence)
        bool sel = false;
#pragma unroll
        for (int k = 0; k < K_; k++) {
            float cand = sel ? -INFINITY : score;
            float m = cand;
#pragma unroll
            for (int o = 8; o; o >>= 1)
                m = fmaxf(m, __shfl_xor_sync(0xffffffffu, m, o, 16));
            unsigned bal = __ballot_sync(0xffffffffu, !sel && score == m) & 0xffffu;
            int best = __ffs(bal) - 1;
            if (lane == best) sel = true;
        }

        float mh = sel ? h : -INFINITY;
#pragma unroll
        for (int o = 8; o; o >>= 1)
            mh = fmaxf(mh, __shfl_xor_sync(0xffffffffu, mh, o, 16));
        float g = sel ? expf(h - mh) : 0.0f;
        float gs = g;
#pragma unroll
        for (int o = 8; o; o >>= 1) gs += __shfl_xor_sync(0xffffffffu, gs, o, 16);

        if (act) out[b * E_ + lane] = g / gs;
    }

    if (tid == 0) g_count[b] = 0;   // reset for next graph replay
}

// ---------------------------------------------------------------------------
extern "C" void kernel_launch(void* const* d_in, const int* in_sizes, int n_in,
                              void* d_out, int out_size) {
    const float* x  = (const float*)d_in[0];
    const float* W0 = (const float*)d_in[1];
    const float* b0 = (const float*)d_in[2];
    const float* W1 = (const float*)d_in[3];
    const float* b1 = (const float*)d_in[4];
    float* out = (float*)d_out;

    // Host-side objects created once (no device memory involved).
    static cudaStream_t side = nullptr;
    static cudaEvent_t  evF = nullptr, evJ = nullptr;
    if (!side) {
        cudaStreamCreateWithFlags(&side, cudaStreamNonBlocking);
        cudaEventCreateWithFlags(&evF, cudaEventDisableTiming);
        cudaEventCreateWithFlags(&evJ, cudaEventDisableTiming);
    }

    // Fork: gate runs on a parallel graph branch, concurrent with pool.
    cudaEventRecord(evF, 0);
    cudaStreamWaitEvent(side, evF, 0);

    pool_kernel<<<(B_ * C_) / ROWS_PER_BLK, 256>>>(x);
    gate_kernel<<<B_, 512, 0, side>>>(W0, b0, W1, b1, out);

    // Join: default stream waits for the gate branch.
    cudaEventRecord(evJ, side);
    cudaStreamWaitEvent(0, evJ, 0);
}

// round 17
// speedup vs baseline: 1.0260x; 1.0260x over previous
#include <cuda_runtime.h>
#include <math.h>

#define B_  64
#define C_  512
#define HW_ 4096      // 64*64
#define E_  16
#define K_  4

// Scratch for pooled [B, C] (device global — no allocation)
__device__ float g_pooled[B_ * C_];

// ---------------------------------------------------------------------------
// Kernel 1: pooled[b,c] = max(x) + mean(x) over each row of 4096 floats.
// Split-8: block = 256 threads = 8 warps = ONE row; each warp streams a
// 512-float eighth (4 front-batched LDG.128/lane, __ldcs evict-first).
// ---------------------------------------------------------------------------
__global__ __launch_bounds__(256) void pool_kernel(const float* __restrict__ x) {
    const int tid  = threadIdx.x;
    const int w    = tid >> 5;          // warp 0..7 = eighth of the row
    const int lane = tid & 31;
    const int row  = blockIdx.x;        // one row per block

    __shared__ float2 sh[8];            // per-warp (max, sum) partials

    // eighth = 512 floats = 128 float4; 4 float4 per lane, front-batched
    const float4* __restrict__ p =
        reinterpret_cast<const float4*>(x + (size_t)row * HW_) + w * 128 + lane;

    float4 a = __ldcs(p);               // streaming: evict-first
    float4 b = __ldcs(p + 32);
    float4 c = __ldcs(p + 64);
    float4 d = __ldcs(p + 96);

    float mx0 = fmaxf(fmaxf(a.x, a.y), fmaxf(a.z, a.w));
    float sm0 = (a.x + a.y) + (a.z + a.w);
    float mx1 = fmaxf(fmaxf(b.x, b.y), fmaxf(b.z, b.w));
    float sm1 = (b.x + b.y) + (b.z + b.w);
    mx0 = fmaxf(mx0, fmaxf(fmaxf(c.x, c.y), fmaxf(c.z, c.w)));
    sm0 += (c.x + c.y) + (c.z + c.w);
    mx1 = fmaxf(mx1, fmaxf(fmaxf(d.x, d.y), fmaxf(d.z, d.w)));
    sm1 += (d.x + d.y) + (d.z + d.w);

    float mx = fmaxf(mx0, mx1);
    float sm = sm0 + sm1;
#pragma unroll
    for (int o = 16; o; o >>= 1) {
        mx = fmaxf(mx, __shfl_xor_sync(0xffffffffu, mx, o));
        sm += __shfl_xor_sync(0xffffffffu, sm, o);
    }
    if (lane == 0) sh[w] = make_float2(mx, sm);
    __syncthreads();

    if (tid == 0) {                     // combine the 8 eighths
        float m = sh[0].x, s = sh[0].y;
#pragma unroll
        for (int i = 1; i < 8; i++) { m = fmaxf(m, sh[i].x); s += sh[i].y; }
        g_pooled[row] = m + s * (1.0f / HW_);
    }
}

// ---------------------------------------------------------------------------
// Kernel 2: gate (champion form). 64 blocks x 512 threads; warp e = expert e,
// all loads front-batched; warp 0 runs the warp-parallel epilogue.
// ---------------------------------------------------------------------------
__global__ __launch_bounds__(512) void gate_kernel(const float* __restrict__ W0,
                                                   const float* __restrict__ b0,
                                                   const float* __restrict__ W1,
                                                   const float* __restrict__ b1,
                                                   float* __restrict__ out) {
    const int b    = blockIdx.x;
    const int tid  = threadIdx.x;
    const int e    = tid >> 5;     // expert = warp id (0..15)
    const int lane = tid & 31;

    __shared__ float sh_h[E_];
    __shared__ float sh_n[E_];

    const float4* __restrict__ w0p =
        reinterpret_cast<const float4*>(W0 + e * C_) + lane;
    const float4* __restrict__ w1p =
        reinterpret_cast<const float4*>(W1 + e * C_) + lane;
    const float4* __restrict__ prow =
        reinterpret_cast<const float4*>(g_pooled + b * C_) + lane;

    float4 w0r[4], w1r[4], pv[4];
#pragma unroll
    for (int i = 0; i < 4; i++) pv[i]  = prow[i * 32];
#pragma unroll
    for (int i = 0; i < 4; i++) w0r[i] = w0p[i * 32];
#pragma unroll
    for (int i = 0; i < 4; i++) w1r[i] = w1p[i * 32];

    float d0 = 0.0f, d1 = 0.0f;
#pragma unroll
    for (int i = 0; i < 4; i++) {
        d0 = fmaf(pv[i].x, w0r[i].x, d0); d0 = fmaf(pv[i].y, w0r[i].y, d0);
        d0 = fmaf(pv[i].z, w0r[i].z, d0); d0 = fmaf(pv[i].w, w0r[i].w, d0);
        d1 = fmaf(pv[i].x, w1r[i].x, d1); d1 = fmaf(pv[i].y, w1r[i].y, d1);
        d1 = fmaf(pv[i].z, w1r[i].z, d1); d1 = fmaf(pv[i].w, w1r[i].w, d1);
    }
#pragma unroll
    for (int o = 16; o; o >>= 1) {
        d0 += __shfl_xor_sync(0xffffffffu, d0, o);
        d1 += __shfl_xor_sync(0xffffffffu, d1, o);
    }
    if (lane == 0) {
        float hv = d0 + b0[e];
        sh_h[e] = (hv >= 0.0f) ? hv : 0.2f * hv;                 // LeakyReLU(0.2)
        float z = d1 + b1[e];
        sh_n[e] = fmaxf(z, 0.0f) + log1pf(expf(-fabsf(z)));      // softplus
    }
    __syncthreads();

    // ------------- warp-parallel epilogue (warp 0; lane i = expert i) -------
    if (tid < 32) {
        const bool act = lane < E_;
        float h  = act ? sh_h[lane] : 0.0f;
        float nz = act ? sh_n[lane] : 0.0f;

        float s = nz;
#pragma unroll
        for (int o = 8; o; o >>= 1) s += __shfl_xor_sync(0xffffffffu, s, o, 16);
        const float mu = s * (1.0f / E_);

        float d = nz - mu;
        float v = d * d;
#pragma unroll
        for (int o = 8; o; o >>= 1) v += __shfl_xor_sync(0xffffffffu, v, o, 16);
        const float sd = sqrtf(v * (1.0f / (E_ - 1)));   // ddof=1

        float score = act ? (h + d / sd) : -INFINITY;

        // top-K via max + ballot; lowest lane wins ties (= first occurrence)
        bool sel = false;
#pragma unroll
        for (int k = 0; k < K_; k++) {
            float cand = sel ? -INFINITY : score;
            float m = cand;
#pragma unroll
            for (int o = 8; o; o >>= 1)
                m = fmaxf(m, __shfl_xor_sync(0xffffffffu, m, o, 16));
            unsigned bal = __ballot_sync(0xffffffffu, !sel && score == m) & 0xffffu;
            int best = __ffs(bal) - 1;
            if (lane == best) sel = true;
        }

        float mh = sel ? h : -INFINITY;
#pragma unroll
        for (int o = 8; o; o >>= 1)
            mh = fmaxf(mh, __shfl_xor_sync(0xffffffffu, mh, o, 16));
        float g = sel ? expf(h - mh) : 0.0f;
        float gs = g;
#pragma unroll
        for (int o = 8; o; o >>= 1) gs += __shfl_xor_sync(0xffffffffu, gs, o, 16);

        if (act) out[b * E_ + lane] = g / gs;
    }
}

// ---------------------------------------------------------------------------
extern "C" void kernel_launch(void* const* d_in, const int* in_sizes, int n_in,
                              void* d_out, int out_size) {
    const float* x  = (const float*)d_in[0];
    const float* W0 = (const float*)d_in[1];
    const float* b0 = (const float*)d_in[2];
    const float* W1 = (const float*)d_in[3];
    const float* b1 = (const float*)d_in[4];
    float* out = (float*)d_out;

    pool_kernel<<<B_ * C_, 256>>>(x);       // 1 row per block, split-8
    gate_kernel<<<B_, 512>>>(W0, b0, W1, b1, out);
}